// round 13
// baseline (speedup 1.0000x reference)
#include <cuda_runtime.h>

typedef unsigned long long ull;

#define Tn 512
#define BT 32768   // B*T

// ---------------- static device scratch (no allocations allowed) -----------
__device__ float g_xgA[(size_t)BT * 2048];
__device__ float g_xgB[(size_t)BT * 2048];
__device__ float g_x1 [(size_t)BT * 1024];
__device__ float g_din[(size_t)BT * 1280];
__device__ float g_yd0[(size_t)BT * 512];
__device__ float g_yd1[(size_t)BT * 512];
__device__ float g_hA0[64 * 512], g_hA1[64 * 512];
__device__ float g_hB0[64 * 512], g_hB1[64 * 512];
__device__ float g_h0f[64 * 512], g_c0f[64 * 512];
__device__ float g_h0b[64 * 512], g_c0b[64 * 512];
__device__ unsigned g_arr, g_rel;

// ---------------- helpers ----------------
__device__ __forceinline__ ull fma2_(ull a, ull b, ull c) {
    ull d;
    asm("fma.rn.f32x2 %0, %1, %2, %3;" : "=l"(d) : "l"(a), "l"(b), "l"(c));
    return d;
}
__device__ __forceinline__ float sum2_(ull v) {
    return __uint_as_float((unsigned)v) + __uint_as_float((unsigned)(v >> 32));
}
__device__ __forceinline__ float sig_(float x) { return 1.f / (1.f + expf(-x)); }

// ---------------- tiny utility kernels ----------------
__global__ void k_embed(const int* __restrict__ x, const float* __restrict__ emb,
                        float* __restrict__ din) {
    int i = blockIdx.x * blockDim.x + threadIdx.x;   // BT*64 float4s
    if (i >= BT * 64) return;
    int bt = i >> 6, e4 = i & 63;
    float4 v = ((const float4*)(emb + (size_t)x[bt] * 256))[e4];
    ((float4*)(din + (size_t)bt * 1280))[e4] = v;
}
__global__ void k_zero(float* p, int n) {
    int i = blockIdx.x * blockDim.x + threadIdx.x;
    if (i < n) p[i] = 0.f;
}
__global__ void k_copy(float* d, const float* s, int n) {
    int i = blockIdx.x * blockDim.x + threadIdx.x;
    if (i < n) d[i] = s[i];
}
__global__ void k_rst() {
    if (threadIdx.x == 0) { g_arr = 0u; g_rel = 0u; }
}

// ---------------- GEMM: C[M,N] = A[M,K] @ W[N,K]^T + b1 (+ b2) -------------
__global__ void __launch_bounds__(256) k_gemm(
    const float* __restrict__ A, int lda,
    const float* __restrict__ W, int K,
    const float* __restrict__ b1, const float* __restrict__ b2,
    float* __restrict__ C, int ldc)
{
    __shared__ __align__(16) float As[64][18];
    __shared__ __align__(16) float Ws[64][18];
    int m0 = blockIdx.y * 64, n0 = blockIdx.x * 64;
    int tid = threadIdx.x;
    int lr = tid >> 2, lc = (tid & 3) * 4;
    int tm = tid >> 4, tn = tid & 15;

    ull acc[4][4];
#pragma unroll
    for (int i = 0; i < 4; i++)
#pragma unroll
        for (int j = 0; j < 4; j++) acc[i][j] = 0ull;

    const float* Ab = A + (size_t)(m0 + lr) * lda + lc;
    const float* Wb = W + (size_t)(n0 + lr) * K + lc;

    for (int k0 = 0; k0 < K; k0 += 16) {
        float4 av = *(const float4*)(Ab + k0);
        float4 wv = *(const float4*)(Wb + k0);
        As[lr][lc + 0] = av.x; As[lr][lc + 1] = av.y;
        As[lr][lc + 2] = av.z; As[lr][lc + 3] = av.w;
        Ws[lr][lc + 0] = wv.x; Ws[lr][lc + 1] = wv.y;
        Ws[lr][lc + 2] = wv.z; Ws[lr][lc + 3] = wv.w;
        __syncthreads();
#pragma unroll
        for (int kk = 0; kk < 8; kk++) {
            ull a2[4], w2[4];
#pragma unroll
            for (int i = 0; i < 4; i++)
                a2[i] = *(const ull*)&As[tm * 4 + i][kk * 2];
#pragma unroll
            for (int j = 0; j < 4; j++)
                w2[j] = *(const ull*)&Ws[tn + 16 * j][kk * 2];
#pragma unroll
            for (int i = 0; i < 4; i++)
#pragma unroll
                for (int j = 0; j < 4; j++)
                    acc[i][j] = fma2_(a2[i], w2[j], acc[i][j]);
        }
        __syncthreads();
    }
#pragma unroll
    for (int j = 0; j < 4; j++) {
        int n = n0 + tn + 16 * j;
        float bias = b1[n] + (b2 ? b2[n] : 0.f);
#pragma unroll
        for (int i = 0; i < 4; i++) {
            int m = m0 + tm * 4 + i;
            C[(size_t)m * ldc + n] = sum2_(acc[i][j]) + bias;
        }
    }
}

// ---------------- persistent LSTM scan v2 ----------------
// 128 threads (4 warps). Thread owns all 4 gates of ONE j for RB batch rows.
// JPB = gate-columns per block (32 enc: 8 j/block, 64 blk/dir; 16 dec: 4 j, 128 blk).
// h_s [64][514] (stride even -> 8B aligned; lanes on consecutive rows -> CF).
// w_s ull[JPB][257]: row = jloc*4+g, element k2 = (W[g*512+j][2k2], W[..][2k2+1]).
// W staged once per scan; c in registers; xg prefetched before the k2 loop.
#define HS 514
#define WSU 257
#define SMEM_SC(JPB) ((64 * HS) * 4 + (JPB) * WSU * 8)

struct ScanP {
    const float* xg;    // [B*T][2048], includes both biases
    const float* Whh;   // [2048][512]
    const float* cin;   // [64*512] initial c, or nullptr -> 0
    float* hb0;         // ping buffer 0 (pre-filled with initial h)
    float* hb1;         // ping buffer 1
    float* cfin;        // final c out, or nullptr
    float* y;           // output base
    int ycol, ystr, rev;
};

template<int JPB>
__global__ void __launch_bounds__(128) k_scan(ScanP pa, ScanP pb, int nb) {
    constexpr int NWJ = JPB / 16;        // warps along j: 2 enc, 1 dec
    constexpr int NWB = 4 / NWJ;         // warps along b: 2 enc, 4 dec
    constexpr int BPW = 64 / NWB;        // 32, 16
    constexpr int RB  = BPW / 8;         // 4, 2
    constexpr int NJ  = JPB / 4;         // j per block: 8, 4

    ScanP p = blockIdx.y ? pb : pa;
    extern __shared__ __align__(16) float sm[];
    float* h_s = sm;                              // [64][HS]
    ull*   w_u = (ull*)(sm + 64 * HS);            // [JPB][WSU]

    int tid = threadIdx.x;
    int w = tid >> 5, lane = tid & 31;
    int lb = lane >> 2, lj = lane & 3;            // 8 x 4
    int wj = w / NWB, wb = w % NWB;
    int jloc = wj * 4 + lj;                       // 0..NJ-1
    int j = blockIdx.x * NJ + jloc;

    // stage W once per scan
    for (int idx = tid; idx < JPB * 128; idx += 128) {
        int r = idx >> 7, c4 = idx & 127;
        int jl = r >> 2, g = r & 3;
        float4 v = ((const float4*)(p.Whh +
                    (size_t)(g * 512 + blockIdx.x * NJ + jl) * 512))[c4];
        ull* dst = w_u + (size_t)r * WSU + c4 * 2;
        dst[0] = ((const ull*)&v)[0];
        dst[1] = ((const ull*)&v)[1];
    }

    float cc[RB];
    int brow[RB];
#pragma unroll
    for (int i = 0; i < RB; i++) {
        brow[i] = wb * BPW + i * 8 + lb;
        cc[i] = p.cin ? p.cin[brow[i] * 512 + j] : 0.f;
    }

    const ull* wp0 = w_u + (size_t)(jloc * 4 + 0) * WSU;
    const ull* wp1 = w_u + (size_t)(jloc * 4 + 1) * WSU;
    const ull* wp2 = w_u + (size_t)(jloc * 4 + 2) * WSU;
    const ull* wp3 = w_u + (size_t)(jloc * 4 + 3) * WSU;

    for (int t = 0; t < Tn; t++) {
        const float* hin = (t & 1) ? p.hb1 : p.hb0;
        float* hout      = (t & 1) ? p.hb0 : p.hb1;
        int ta = p.rev ? (Tn - 1 - t) : t;

        // prefetch xg gate biases for this step (consumed in the epilogue)
        float xv[RB][4];
#pragma unroll
        for (int i = 0; i < RB; i++) {
            const float* xr = p.xg + ((size_t)brow[i] * Tn + ta) * 2048 + j;
#pragma unroll
            for (int g = 0; g < 4; g++) xv[i][g] = __ldcg(xr + g * 512);
        }

        // stage h: 64 x 512 floats -> h_s[64][HS]
        for (int idx = tid; idx < 64 * 128; idx += 128) {
            int r = idx >> 7, c4 = idx & 127;
            float4 v = __ldcg((const float4*)(hin + r * 512) + c4);
            ull* dst = (ull*)(h_s + r * HS) + c4 * 2;
            dst[0] = ((const ull*)&v)[0];
            dst[1] = ((const ull*)&v)[1];
        }
        __syncthreads();

        ull acc[RB][4];
#pragma unroll
        for (int i = 0; i < RB; i++)
#pragma unroll
            for (int g = 0; g < 4; g++) acc[i][g] = 0ull;

        const ull* hp[RB];
#pragma unroll
        for (int i = 0; i < RB; i++)
            hp[i] = (const ull*)(h_s + brow[i] * HS);

#pragma unroll 2
        for (int k2 = 0; k2 < 256; k2++) {
            ull wv0 = wp0[k2], wv1 = wp1[k2], wv2 = wp2[k2], wv3 = wp3[k2];
#pragma unroll
            for (int i = 0; i < RB; i++) {
                ull hv = hp[i][k2];
                acc[i][0] = fma2_(hv, wv0, acc[i][0]);
                acc[i][1] = fma2_(hv, wv1, acc[i][1]);
                acc[i][2] = fma2_(hv, wv2, acc[i][2]);
                acc[i][3] = fma2_(hv, wv3, acc[i][3]);
            }
        }

        // epilogue: this thread has all 4 gates of (brow[i], j)
#pragma unroll
        for (int i = 0; i < RB; i++) {
            float gi = sum2_(acc[i][0]) + xv[i][0];
            float gf = sum2_(acc[i][1]) + xv[i][1];
            float gg = sum2_(acc[i][2]) + xv[i][2];
            float go = sum2_(acc[i][3]) + xv[i][3];
            cc[i] = sig_(gf) * cc[i] + sig_(gi) * tanhf(gg);
            float hv = sig_(go) * tanhf(cc[i]);
            hout[brow[i] * 512 + j] = hv;
            p.y[((size_t)brow[i] * Tn + ta) * p.ystr + p.ycol + j] = hv;
        }

        // software grid barrier (all blocks co-resident: 1 block/SM)
        __threadfence();
        __syncthreads();
        if (tid == 0) {
            unsigned n = atomicAdd(&g_arr, 1u) + 1u;
            if (n == (unsigned)nb * (unsigned)(t + 1)) {
                atomicExch(&g_rel, (unsigned)(t + 1));
            }
            volatile unsigned* rp = &g_rel;
            while (*rp < (unsigned)(t + 1)) { }
            __threadfence();
        }
        __syncthreads();
    }

    if (p.cfin) {
#pragma unroll
        for (int i = 0; i < RB; i++)
            p.cfin[brow[i] * 512 + j] = cc[i];
    }
}

// ---------------- host orchestration ----------------
extern "C" void kernel_launch(void* const* d_in, const int* in_sizes, int n_in,
                              void* d_out, int out_size) {
    const int*   x   = (const int*)d_in[0];
    const float* emb = (const float*)d_in[1];
    auto F = [&](int i) { return (const float*)d_in[i]; };

    float *xgA, *xgB, *x1, *din, *yd0, *yd1;
    float *hA0, *hA1, *hB0, *hB1, *h0f, *c0f, *h0b, *c0b;
    cudaGetSymbolAddress((void**)&xgA, g_xgA);
    cudaGetSymbolAddress((void**)&xgB, g_xgB);
    cudaGetSymbolAddress((void**)&x1,  g_x1);
    cudaGetSymbolAddress((void**)&din, g_din);
    cudaGetSymbolAddress((void**)&yd0, g_yd0);
    cudaGetSymbolAddress((void**)&yd1, g_yd1);
    cudaGetSymbolAddress((void**)&hA0, g_hA0);
    cudaGetSymbolAddress((void**)&hA1, g_hA1);
    cudaGetSymbolAddress((void**)&hB0, g_hB0);
    cudaGetSymbolAddress((void**)&hB1, g_hB1);
    cudaGetSymbolAddress((void**)&h0f, g_h0f);
    cudaGetSymbolAddress((void**)&c0f, g_c0f);
    cudaGetSymbolAddress((void**)&h0b, g_h0b);
    cudaGetSymbolAddress((void**)&c0b, g_c0b);

    cudaFuncSetAttribute(k_scan<32>, cudaFuncAttributeMaxDynamicSharedMemorySize, SMEM_SC(32));
    cudaFuncSetAttribute(k_scan<16>, cudaFuncAttributeMaxDynamicSharedMemorySize, SMEM_SC(16));

    const int SN = 64 * 512;
    dim3 gGemm(2048 / 64, BT / 64);

    auto mkP = [](const float* xg, const float* Whh, const float* cin,
                  float* hb0, float* hb1, float* cfin,
                  float* y, int ycol, int ystr, int rev) {
        ScanP p; p.xg = xg; p.Whh = Whh; p.cin = cin;
        p.hb0 = hb0; p.hb1 = hb1; p.cfin = cfin;
        p.y = y; p.ycol = ycol; p.ystr = ystr; p.rev = rev;
        return p;
    };

    // 1. embedding -> din[:, 0:256]
    k_embed<<<(BT * 64 + 255) / 256, 256>>>(x, emb, din);

    // 2. encoder layer 0 (fwd + bwd)
    k_gemm<<<gGemm, 256>>>(din, 1280, F(2), 256, F(4), F(5), xgA, 2048);
    k_gemm<<<gGemm, 256>>>(din, 1280, F(6), 256, F(8), F(9), xgB, 2048);
    k_zero<<<128, 256>>>(hA0, SN);
    k_zero<<<128, 256>>>(hB0, SN);
    k_rst<<<1, 32>>>();
    {
        ScanP pa = mkP(xgA, F(3), nullptr, hA0, hA1, c0f, x1, 0, 1024, 0);
        ScanP pb = mkP(xgB, F(7), nullptr, hB0, hB1, c0b, x1, 512, 1024, 1);
        k_scan<32><<<dim3(64, 2), 128, SMEM_SC(32)>>>(pa, pb, 128);
    }
    // final h of layer 0 is in buffer 0 (t=511 writes hb0)
    k_copy<<<128, 256>>>(h0f, hA0, SN);
    k_copy<<<128, 256>>>(h0b, hB0, SN);

    // 3. encoder layer 1 (fwd + bwd), outputs into din cols 256 / 768
    k_gemm<<<gGemm, 256>>>(x1, 1024, F(10), 1024, F(12), F(13), xgA, 2048);
    k_gemm<<<gGemm, 256>>>(x1, 1024, F(14), 1024, F(16), F(17), xgB, 2048);
    k_zero<<<128, 256>>>(hA0, SN);
    k_zero<<<128, 256>>>(hB0, SN);
    k_rst<<<1, 32>>>();
    {
        ScanP pa = mkP(xgA, F(11), nullptr, hA0, hA1, nullptr, din, 256, 1280, 0);
        ScanP pb = mkP(xgB, F(15), nullptr, hB0, hB1, nullptr, din, 768, 1280, 1);
        k_scan<32><<<dim3(64, 2), 128, SMEM_SC(32)>>>(pa, pb, 128);
    }

    // 4. decoder layer 0 (init = enc l0 fwd final state), 128 blocks (full chip)
    k_gemm<<<gGemm, 256>>>(din, 1280, F(18), 1280, F(20), F(21), xgA, 2048);
    k_copy<<<128, 256>>>(hA0, h0f, SN);
    k_rst<<<1, 32>>>();
    {
        ScanP pa = mkP(xgA, F(19), c0f, hA0, hA1, nullptr, yd0, 0, 512, 0);
        k_scan<16><<<dim3(128, 1), 128, SMEM_SC(16)>>>(pa, pa, 128);
    }

    // 5. decoder layer 1 (init = enc l0 bwd final state)
    k_gemm<<<gGemm, 256>>>(yd0, 512, F(22), 512, F(24), F(25), xgA, 2048);
    k_copy<<<128, 256>>>(hA0, h0b, SN);
    k_rst<<<1, 32>>>();
    {
        ScanP pa = mkP(xgA, F(23), c0b, hA0, hA1, nullptr, yd1, 0, 512, 0);
        k_scan<16><<<dim3(128, 1), 128, SMEM_SC(16)>>>(pa, pa, 128);
    }

    // 6. output projection: logits = yd1 @ out_W^T + out_b  (N = 128)
    k_gemm<<<dim3(128 / 64, BT / 64), 256>>>(yd1, 512, F(26), 512, F(27), nullptr,
                                             (float*)d_out, 128);
}

// round 14
// speedup vs baseline: 1.0461x; 1.0461x over previous
#include <cuda_runtime.h>

typedef unsigned long long ull;

#define Tn 512
#define BT 32768   // B*T

// ---------------- static device scratch (no allocations allowed) -----------
__device__ float g_xgA[(size_t)BT * 2048];
__device__ float g_xgB[(size_t)BT * 2048];
__device__ float g_x1 [(size_t)BT * 1024];
__device__ float g_din[(size_t)BT * 1280];
__device__ float g_yd0[(size_t)BT * 512];
__device__ float g_yd1[(size_t)BT * 512];
__device__ float g_hA0[64 * 512], g_hA1[64 * 512];
__device__ float g_hB0[64 * 512], g_hB1[64 * 512];
__device__ float g_h0f[64 * 512], g_c0f[64 * 512];
__device__ float g_h0b[64 * 512], g_c0b[64 * 512];
__device__ unsigned g_arr, g_rel;

// ---------------- helpers ----------------
__device__ __forceinline__ ull fma2_(ull a, ull b, ull c) {
    ull d;
    asm("fma.rn.f32x2 %0, %1, %2, %3;" : "=l"(d) : "l"(a), "l"(b), "l"(c));
    return d;
}
__device__ __forceinline__ float sum2_(ull v) {
    return __uint_as_float((unsigned)v) + __uint_as_float((unsigned)(v >> 32));
}
__device__ __forceinline__ float sig_(float x) { return 1.f / (1.f + expf(-x)); }

// h row layout: stride 514 floats + 2-float pad when bit4 of row set.
// => for a 32-lane LDS.64 over rows lane (or lane+32), both half-warp
// phases hit 16 distinct banks -> conflict-free (2-cyc floor).
__device__ __forceinline__ int rowoff_(int r) {
    return r * 514 + ((r >> 4) & 1) * 2;
}

// ---------------- tiny utility kernels ----------------
__global__ void k_embed(const int* __restrict__ x, const float* __restrict__ emb,
                        float* __restrict__ din) {
    int i = blockIdx.x * blockDim.x + threadIdx.x;   // BT*64 float4s
    if (i >= BT * 64) return;
    int bt = i >> 6, e4 = i & 63;
    float4 v = ((const float4*)(emb + (size_t)x[bt] * 256))[e4];
    ((float4*)(din + (size_t)bt * 1280))[e4] = v;
}
__global__ void k_zero(float* p, int n) {
    int i = blockIdx.x * blockDim.x + threadIdx.x;
    if (i < n) p[i] = 0.f;
}
__global__ void k_copy(float* d, const float* s, int n) {
    int i = blockIdx.x * blockDim.x + threadIdx.x;
    if (i < n) d[i] = s[i];
}
__global__ void k_rst() {
    if (threadIdx.x == 0) { g_arr = 0u; g_rel = 0u; }
}

// ---------------- GEMM: C[M,N] = A[M,K] @ W[N,K]^T + b1 (+ b2) -------------
__global__ void __launch_bounds__(256) k_gemm(
    const float* __restrict__ A, int lda,
    const float* __restrict__ W, int K,
    const float* __restrict__ b1, const float* __restrict__ b2,
    float* __restrict__ C, int ldc)
{
    __shared__ __align__(16) float As[64][18];
    __shared__ __align__(16) float Ws[64][18];
    int m0 = blockIdx.y * 64, n0 = blockIdx.x * 64;
    int tid = threadIdx.x;
    int lr = tid >> 2, lc = (tid & 3) * 4;
    int tm = tid >> 4, tn = tid & 15;

    ull acc[4][4];
#pragma unroll
    for (int i = 0; i < 4; i++)
#pragma unroll
        for (int j = 0; j < 4; j++) acc[i][j] = 0ull;

    const float* Ab = A + (size_t)(m0 + lr) * lda + lc;
    const float* Wb = W + (size_t)(n0 + lr) * K + lc;

    for (int k0 = 0; k0 < K; k0 += 16) {
        float4 av = *(const float4*)(Ab + k0);
        float4 wv = *(const float4*)(Wb + k0);
        As[lr][lc + 0] = av.x; As[lr][lc + 1] = av.y;
        As[lr][lc + 2] = av.z; As[lr][lc + 3] = av.w;
        Ws[lr][lc + 0] = wv.x; Ws[lr][lc + 1] = wv.y;
        Ws[lr][lc + 2] = wv.z; Ws[lr][lc + 3] = wv.w;
        __syncthreads();
#pragma unroll
        for (int kk = 0; kk < 8; kk++) {
            ull a2[4], w2[4];
#pragma unroll
            for (int i = 0; i < 4; i++)
                a2[i] = *(const ull*)&As[tm * 4 + i][kk * 2];
#pragma unroll
            for (int j = 0; j < 4; j++)
                w2[j] = *(const ull*)&Ws[tn + 16 * j][kk * 2];
#pragma unroll
            for (int i = 0; i < 4; i++)
#pragma unroll
                for (int j = 0; j < 4; j++)
                    acc[i][j] = fma2_(a2[i], w2[j], acc[i][j]);
        }
        __syncthreads();
    }
#pragma unroll
    for (int j = 0; j < 4; j++) {
        int n = n0 + tn + 16 * j;
        float bias = b1[n] + (b2 ? b2[n] : 0.f);
#pragma unroll
        for (int i = 0; i < 4; i++) {
            int m = m0 + tm * 4 + i;
            C[(size_t)m * ldc + n] = sum2_(acc[i][j]) + bias;
        }
    }
}

// ---------------- persistent LSTM scan v3 ----------------
// 256 threads (8 warps, 2/SMSP). Proven v1 skeleton + conflict-free h pad.
// JPB=8 (encoder): warp w owns gate-column j = bx*8 + w, lanes cover batch
//   rows {lane, lane+32}. 64 blocks per direction.
// JPB=4 (decoder): warps (2w',2w'+1) share j = bx*4 + w'; each warp covers
//   32 batch rows (lane + 32*(w&1)). 128 blocks -> full chip.
// W staged once per scan; c in registers; xg prefetched before the k2 loop.
#define HFLOATS (64 * 516)
#define SMEM_SC(JPB) (HFLOATS * 4 + (JPB) * 4 * 512 * 4)

struct ScanP {
    const float* xg;    // [B*T][2048], includes both biases
    const float* Whh;   // [2048][512]
    const float* cin;   // [64*512] initial c, or nullptr -> 0
    float* hb0;         // ping buffer 0 (pre-filled with initial h)
    float* hb1;         // ping buffer 1
    float* cfin;        // final c out, or nullptr
    float* y;           // output base
    int ycol, ystr, rev;
};

template<int JPB>
__global__ void __launch_bounds__(256) k_scan(ScanP pa, ScanP pb, int nb) {
    constexpr int RB = (JPB == 8) ? 2 : 1;   // batch rows per lane

    ScanP p = blockIdx.y ? pb : pa;
    extern __shared__ __align__(16) float sm[];
    float* h_s = sm;                       // padded [64] rows, rowoff_()
    float* w_s = sm + HFLOATS;             // [JPB*4][512]

    int tid = threadIdx.x;
    int w = tid >> 5, lane = tid & 31;
    int jloc = (JPB == 8) ? w : (w >> 1);
    int j = blockIdx.x * JPB + jloc;
    int r0 = (JPB == 8) ? lane : (lane + 32 * (w & 1));

    // stage Whh rows for this block's JPB j's, once per scan
    for (int idx = tid; idx < JPB * 4 * 128; idx += 256) {
        int r = idx >> 7, c4 = idx & 127;
        int jl = r >> 2, g = r & 3;
        float4 v = ((const float4*)(p.Whh +
                    (size_t)(g * 512 + blockIdx.x * JPB + jl) * 512))[c4];
        ((float4*)(w_s + (size_t)r * 512))[c4] = v;
    }

    // c state in registers
    float cc[RB];
#pragma unroll
    for (int i = 0; i < RB; i++)
        cc[i] = p.cin ? p.cin[(r0 + 32 * i) * 512 + j] : 0.f;

    const ull* wp0 = (const ull*)(w_s + (jloc * 4 + 0) * 512);
    const ull* wp1 = (const ull*)(w_s + (jloc * 4 + 1) * 512);
    const ull* wp2 = (const ull*)(w_s + (jloc * 4 + 2) * 512);
    const ull* wp3 = (const ull*)(w_s + (jloc * 4 + 3) * 512);

    for (int t = 0; t < Tn; t++) {
        const float* hin = (t & 1) ? p.hb1 : p.hb0;
        float* hout      = (t & 1) ? p.hb0 : p.hb1;
        int ta = p.rev ? (Tn - 1 - t) : t;

        // prefetch xg gate values (hidden behind staging + FMA loop)
        float xv[RB][4];
#pragma unroll
        for (int i = 0; i < RB; i++) {
            const float* xr = p.xg + ((size_t)(r0 + 32 * i) * Tn + ta) * 2048 + j;
#pragma unroll
            for (int g = 0; g < 4; g++) xv[i][g] = __ldcg(xr + g * 512);
        }

        // stage h (bypass L1: other SMs wrote it last step)
        for (int idx = tid; idx < 64 * 128; idx += 256) {
            int r = idx >> 7, c4 = idx & 127;
            float4 v = __ldcg((const float4*)(hin + r * 512) + c4);
            ull* dst = (ull*)(h_s + rowoff_(r)) + c4 * 2;
            dst[0] = ((const ull*)&v)[0];
            dst[1] = ((const ull*)&v)[1];
        }
        __syncthreads();

        const ull* hq0 = (const ull*)(h_s + rowoff_(r0));
        ull a00 = 0, a01 = 0, a02 = 0, a03 = 0;
        if (JPB == 8) {
            const ull* hq1 = (const ull*)(h_s + rowoff_(r0 + 32));
            ull a10 = 0, a11 = 0, a12 = 0, a13 = 0;
#pragma unroll 4
            for (int k2 = 0; k2 < 256; k2++) {
                ull h0 = hq0[k2], h1 = hq1[k2];
                ull w0 = wp0[k2], w1 = wp1[k2], w2v = wp2[k2], w3 = wp3[k2];
                a00 = fma2_(h0, w0, a00); a01 = fma2_(h0, w1, a01);
                a02 = fma2_(h0, w2v, a02); a03 = fma2_(h0, w3, a03);
                a10 = fma2_(h1, w0, a10); a11 = fma2_(h1, w1, a11);
                a12 = fma2_(h1, w2v, a12); a13 = fma2_(h1, w3, a13);
            }
            // epilogue row 1
            {
                float gi = sum2_(a10) + xv[1][0];
                float gf = sum2_(a11) + xv[1][1];
                float gg = sum2_(a12) + xv[1][2];
                float go = sum2_(a13) + xv[1][3];
                cc[1] = sig_(gf) * cc[1] + sig_(gi) * tanhf(gg);
                float hv = sig_(go) * tanhf(cc[1]);
                int b = r0 + 32;
                hout[b * 512 + j] = hv;
                p.y[((size_t)b * Tn + ta) * p.ystr + p.ycol + j] = hv;
            }
        } else {
#pragma unroll 4
            for (int k2 = 0; k2 < 256; k2++) {
                ull h0 = hq0[k2];
                a00 = fma2_(h0, wp0[k2], a00);
                a01 = fma2_(h0, wp1[k2], a01);
                a02 = fma2_(h0, wp2[k2], a02);
                a03 = fma2_(h0, wp3[k2], a03);
            }
        }
        // epilogue row 0
        {
            float gi = sum2_(a00) + xv[0][0];
            float gf = sum2_(a01) + xv[0][1];
            float gg = sum2_(a02) + xv[0][2];
            float go = sum2_(a03) + xv[0][3];
            cc[0] = sig_(gf) * cc[0] + sig_(gi) * tanhf(gg);
            float hv = sig_(go) * tanhf(cc[0]);
            hout[r0 * 512 + j] = hv;
            p.y[((size_t)r0 * Tn + ta) * p.ystr + p.ycol + j] = hv;
        }

        // software grid barrier (all blocks co-resident: 1 block/SM)
        __threadfence();
        __syncthreads();
        if (tid == 0) {
            unsigned n = atomicAdd(&g_arr, 1u) + 1u;
            if (n == (unsigned)nb * (unsigned)(t + 1)) {
                atomicExch(&g_rel, (unsigned)(t + 1));
            }
            volatile unsigned* rp = &g_rel;
            while (*rp < (unsigned)(t + 1)) { }
            __threadfence();
        }
        __syncthreads();
    }

    if (p.cfin) {
#pragma unroll
        for (int i = 0; i < RB; i++)
            p.cfin[(r0 + 32 * i) * 512 + j] = cc[i];
    }
}

// ---------------- host orchestration ----------------
extern "C" void kernel_launch(void* const* d_in, const int* in_sizes, int n_in,
                              void* d_out, int out_size) {
    const int*   x   = (const int*)d_in[0];
    const float* emb = (const float*)d_in[1];
    auto F = [&](int i) { return (const float*)d_in[i]; };

    float *xgA, *xgB, *x1, *din, *yd0, *yd1;
    float *hA0, *hA1, *hB0, *hB1, *h0f, *c0f, *h0b, *c0b;
    cudaGetSymbolAddress((void**)&xgA, g_xgA);
    cudaGetSymbolAddress((void**)&xgB, g_xgB);
    cudaGetSymbolAddress((void**)&x1,  g_x1);
    cudaGetSymbolAddress((void**)&din, g_din);
    cudaGetSymbolAddress((void**)&yd0, g_yd0);
    cudaGetSymbolAddress((void**)&yd1, g_yd1);
    cudaGetSymbolAddress((void**)&hA0, g_hA0);
    cudaGetSymbolAddress((void**)&hA1, g_hA1);
    cudaGetSymbolAddress((void**)&hB0, g_hB0);
    cudaGetSymbolAddress((void**)&hB1, g_hB1);
    cudaGetSymbolAddress((void**)&h0f, g_h0f);
    cudaGetSymbolAddress((void**)&c0f, g_c0f);
    cudaGetSymbolAddress((void**)&h0b, g_h0b);
    cudaGetSymbolAddress((void**)&c0b, g_c0b);

    cudaFuncSetAttribute(k_scan<8>, cudaFuncAttributeMaxDynamicSharedMemorySize, SMEM_SC(8));
    cudaFuncSetAttribute(k_scan<4>, cudaFuncAttributeMaxDynamicSharedMemorySize, SMEM_SC(4));

    const int SN = 64 * 512;
    dim3 gGemm(2048 / 64, BT / 64);

    auto mkP = [](const float* xg, const float* Whh, const float* cin,
                  float* hb0, float* hb1, float* cfin,
                  float* y, int ycol, int ystr, int rev) {
        ScanP p; p.xg = xg; p.Whh = Whh; p.cin = cin;
        p.hb0 = hb0; p.hb1 = hb1; p.cfin = cfin;
        p.y = y; p.ycol = ycol; p.ystr = ystr; p.rev = rev;
        return p;
    };

    // 1. embedding -> din[:, 0:256]
    k_embed<<<(BT * 64 + 255) / 256, 256>>>(x, emb, din);

    // 2. encoder layer 0 (fwd + bwd)
    k_gemm<<<gGemm, 256>>>(din, 1280, F(2), 256, F(4), F(5), xgA, 2048);
    k_gemm<<<gGemm, 256>>>(din, 1280, F(6), 256, F(8), F(9), xgB, 2048);
    k_zero<<<128, 256>>>(hA0, SN);
    k_zero<<<128, 256>>>(hB0, SN);
    k_rst<<<1, 32>>>();
    {
        ScanP pa = mkP(xgA, F(3), nullptr, hA0, hA1, c0f, x1, 0, 1024, 0);
        ScanP pb = mkP(xgB, F(7), nullptr, hB0, hB1, c0b, x1, 512, 1024, 1);
        k_scan<8><<<dim3(64, 2), 256, SMEM_SC(8)>>>(pa, pb, 128);
    }
    // final h of layer 0 is in buffer 0 (t=511 writes hb0)
    k_copy<<<128, 256>>>(h0f, hA0, SN);
    k_copy<<<128, 256>>>(h0b, hB0, SN);

    // 3. encoder layer 1 (fwd + bwd), outputs into din cols 256 / 768
    k_gemm<<<gGemm, 256>>>(x1, 1024, F(10), 1024, F(12), F(13), xgA, 2048);
    k_gemm<<<gGemm, 256>>>(x1, 1024, F(14), 1024, F(16), F(17), xgB, 2048);
    k_zero<<<128, 256>>>(hA0, SN);
    k_zero<<<128, 256>>>(hB0, SN);
    k_rst<<<1, 32>>>();
    {
        ScanP pa = mkP(xgA, F(11), nullptr, hA0, hA1, nullptr, din, 256, 1280, 0);
        ScanP pb = mkP(xgB, F(15), nullptr, hB0, hB1, nullptr, din, 768, 1280, 1);
        k_scan<8><<<dim3(64, 2), 256, SMEM_SC(8)>>>(pa, pb, 128);
    }

    // 4. decoder layer 0 (init = enc l0 fwd final state), 128 blocks full chip
    k_gemm<<<gGemm, 256>>>(din, 1280, F(18), 1280, F(20), F(21), xgA, 2048);
    k_copy<<<128, 256>>>(hA0, h0f, SN);
    k_rst<<<1, 32>>>();
    {
        ScanP pa = mkP(xgA, F(19), c0f, hA0, hA1, nullptr, yd0, 0, 512, 0);
        k_scan<4><<<dim3(128, 1), 256, SMEM_SC(4)>>>(pa, pa, 128);
    }

    // 5. decoder layer 1 (init = enc l0 bwd final state)
    k_gemm<<<gGemm, 256>>>(yd0, 512, F(22), 512, F(24), F(25), xgA, 2048);
    k_copy<<<128, 256>>>(hA0, h0b, SN);
    k_rst<<<1, 32>>>();
    {
        ScanP pa = mkP(xgA, F(23), c0b, hA0, hA1, nullptr, yd1, 0, 512, 0);
        k_scan<4><<<dim3(128, 1), 256, SMEM_SC(4)>>>(pa, pa, 128);
    }

    // 6. output projection: logits = yd1 @ out_W^T + out_b  (N = 128)
    k_gemm<<<dim3(128 / 64, BT / 64), 256>>>(yd1, 512, F(26), 512, F(27), nullptr,
                                             (float*)d_out, 128);
}

// round 16
// speedup vs baseline: 1.7363x; 1.6598x over previous
#include <cuda_runtime.h>

typedef unsigned long long ull;

#define Tn 512
#define BT 32768   // B*T

// ---------------- static device scratch (no allocations allowed) -----------
__device__ float g_xgA[(size_t)BT * 2048];
__device__ float g_xgB[(size_t)BT * 2048];
__device__ float g_x1 [(size_t)BT * 1024];
__device__ float g_din[(size_t)BT * 1280];
__device__ float g_yd0[(size_t)BT * 512];
__device__ float g_yd1[(size_t)BT * 512];
__device__ float g_hA0[64 * 512], g_hA1[64 * 512];
__device__ float g_hB0[64 * 512], g_hB1[64 * 512];
__device__ float g_h0f[64 * 512], g_c0f[64 * 512];
__device__ float g_h0b[64 * 512], g_c0b[64 * 512];
__device__ unsigned g_arr, g_rel;

// ---------------- helpers ----------------
__device__ __forceinline__ ull fma2_(ull a, ull b, ull c) {
    ull d;
    asm("fma.rn.f32x2 %0, %1, %2, %3;" : "=l"(d) : "l"(a), "l"(b), "l"(c));
    return d;
}
__device__ __forceinline__ float sum2_(ull v) {
    return __uint_as_float((unsigned)v) + __uint_as_float((unsigned)(v >> 32));
}
__device__ __forceinline__ float sig_(float x) { return 1.f / (1.f + expf(-x)); }

// ---------------- tiny utility kernels ----------------
__global__ void k_embed(const int* __restrict__ x, const float* __restrict__ emb,
                        float* __restrict__ din) {
    int i = blockIdx.x * blockDim.x + threadIdx.x;   // BT*64 float4s
    if (i >= BT * 64) return;
    int bt = i >> 6, e4 = i & 63;
    float4 v = ((const float4*)(emb + (size_t)x[bt] * 256))[e4];
    ((float4*)(din + (size_t)bt * 1280))[e4] = v;
}
__global__ void k_zero(float* p, int n) {
    int i = blockIdx.x * blockDim.x + threadIdx.x;
    if (i < n) p[i] = 0.f;
}
__global__ void k_copy(float* d, const float* s, int n) {
    int i = blockIdx.x * blockDim.x + threadIdx.x;
    if (i < n) d[i] = s[i];
}
__global__ void k_rst() {
    if (threadIdx.x == 0) { g_arr = 0u; g_rel = 0u; }
}

// ---------------- GEMM v2: C[M,N] = A[M,K] @ W[N,K]^T + b1 (+ b2) ----------
// 128x64 tile, 256 threads, 8x4 register tile of f32x2 accumulators.
// Register-prefetch pipeline hides global-load latency under the FMA loop.
// Smem commits are SCALAR stores (stride-18 rows are not float4-aligned!).
// M % 128 == 0, N % 64 == 0, K % 16 == 0.
__global__ void __launch_bounds__(256) k_gemm(
    const float* __restrict__ A, int lda,
    const float* __restrict__ W, int K,
    const float* __restrict__ b1, const float* __restrict__ b2,
    float* __restrict__ C, int ldc)
{
    __shared__ __align__(16) float As[128][18];
    __shared__ __align__(16) float Ws[64][18];
    int m0 = blockIdx.y * 128, n0 = blockIdx.x * 64;
    int tid = threadIdx.x;
    int tm = tid >> 4, tn = tid & 15;          // 16 x 16 thread grid

    // staging coords: A = 512 float4 (2/thread), B = 256 float4 (1/thread)
    int a0r = tid >> 2,          a0c = (tid & 3) * 4;
    int a1r = (tid + 256) >> 2;
    int br  = tid >> 2,          bc  = (tid & 3) * 4;

    const float* Ap0 = A + (size_t)(m0 + a0r) * lda + a0c;
    const float* Ap1 = A + (size_t)(m0 + a1r) * lda + a0c;
    const float* Wp  = W + (size_t)(n0 + br)  * K   + bc;

    ull acc[8][4];
#pragma unroll
    for (int i = 0; i < 8; i++)
#pragma unroll
        for (int j = 0; j < 4; j++) acc[i][j] = 0ull;

    float4 ra0 = *(const float4*)(Ap0);
    float4 ra1 = *(const float4*)(Ap1);
    float4 rb  = *(const float4*)(Wp);

    for (int k0 = 0; k0 < K; k0 += 16) {
        // commit prefetched slab to smem (scalar stores: rows are 72B apart)
        As[a0r][a0c + 0] = ra0.x; As[a0r][a0c + 1] = ra0.y;
        As[a0r][a0c + 2] = ra0.z; As[a0r][a0c + 3] = ra0.w;
        As[a1r][a0c + 0] = ra1.x; As[a1r][a0c + 1] = ra1.y;
        As[a1r][a0c + 2] = ra1.z; As[a1r][a0c + 3] = ra1.w;
        Ws[br][bc + 0]   = rb.x;  Ws[br][bc + 1]   = rb.y;
        Ws[br][bc + 2]   = rb.z;  Ws[br][bc + 3]   = rb.w;
        __syncthreads();

        // prefetch next slab (latency hidden under the FMA loop)
        float4 na0 = make_float4(0.f, 0.f, 0.f, 0.f);
        float4 na1 = na0, nb = na0;
        if (k0 + 16 < K) {
            na0 = *(const float4*)(Ap0 + k0 + 16);
            na1 = *(const float4*)(Ap1 + k0 + 16);
            nb  = *(const float4*)(Wp  + k0 + 16);
        }

#pragma unroll
        for (int kk = 0; kk < 8; kk++) {
            ull a2[8], w2[4];
#pragma unroll
            for (int i = 0; i < 8; i++)
                a2[i] = *(const ull*)&As[tm * 8 + i][kk * 2];
#pragma unroll
            for (int j = 0; j < 4; j++)
                w2[j] = *(const ull*)&Ws[tn + 16 * j][kk * 2];
#pragma unroll
            for (int i = 0; i < 8; i++)
#pragma unroll
                for (int j = 0; j < 4; j++)
                    acc[i][j] = fma2_(a2[i], w2[j], acc[i][j]);
        }
        __syncthreads();
        ra0 = na0; ra1 = na1; rb = nb;
    }

#pragma unroll
    for (int j = 0; j < 4; j++) {
        int n = n0 + tn + 16 * j;
        float bias = b1[n] + (b2 ? b2[n] : 0.f);
#pragma unroll
        for (int i = 0; i < 8; i++) {
            int m = m0 + tm * 8 + i;
            C[(size_t)m * ldc + n] = sum2_(acc[i][j]) + bias;
        }
    }
}

// ---------------- persistent LSTM scan (v1, measured 51.7 ms total) --------
// grid (64, ndir), block 256 (8 warps). Warp w owns gate-column j = bx*8 + w
// for all 4 gates and all 64 batch rows (2 per lane). Whh tile staged ONCE.
// h re-staged from global (ping-pong) each step; c lives in registers.
// smem: h[64][514] + Whh[32][512]  -> 197120 bytes -> 1 block/SM, 128 blocks
// co-resident on 148 SMs -> software grid barrier is safe.
#define SMEM_SCAN ((64 * 514 + 32 * 512) * 4)

struct ScanP {
    const float* xg;    // [B*T][2048], includes both biases
    const float* Whh;   // [2048][512]
    const float* cin;   // [64*512] initial c, or nullptr -> 0
    float* hb0;         // ping buffer 0 (pre-filled with initial h)
    float* hb1;         // ping buffer 1
    float* cfin;        // final c out, or nullptr
    float* y;           // output base
    int ycol, ystr, rev;
};

__global__ void __launch_bounds__(256) k_scan(ScanP pa, ScanP pb, int nb) {
    ScanP p = blockIdx.y ? pb : pa;
    extern __shared__ __align__(16) float sm[];
    float* h_s = sm;                 // [64][514]
    float* w_s = sm + 64 * 514;      // [32][512], row r = w*4 + g

    int tid = threadIdx.x;
    int w = tid >> 5, lane = tid & 31;
    int jb = blockIdx.x * 8, j = jb + w;

    // stage Whh rows for this block's 8 j's, once per scan
    for (int i = tid; i < 32 * 128; i += 256) {
        int r = i >> 7, c4 = i & 127;
        int wj = r >> 2, g = r & 3;
        float4 v = ((const float4*)(p.Whh + (size_t)(g * 512 + jb + wj) * 512))[c4];
        ((float4*)(w_s + r * 512))[c4] = v;
    }

    // c state in registers
    float cc0 = p.cin ? p.cin[lane * 512 + j] : 0.f;
    float cc1 = p.cin ? p.cin[(lane + 32) * 512 + j] : 0.f;

    const ull* wr0 = (const ull*)(w_s + (w * 4 + 0) * 512);
    const ull* wr1 = (const ull*)(w_s + (w * 4 + 1) * 512);
    const ull* wr2 = (const ull*)(w_s + (w * 4 + 2) * 512);
    const ull* wr3 = (const ull*)(w_s + (w * 4 + 3) * 512);

    for (int t = 0; t < Tn; t++) {
        const float* hin = (t & 1) ? p.hb1 : p.hb0;
        float* hout      = (t & 1) ? p.hb0 : p.hb1;
        int t_act = p.rev ? (Tn - 1 - t) : t;

        // stage h (bypass L1: other SMs wrote it last step)
        for (int i = tid; i < 64 * 128; i += 256) {
            int r = i >> 7, c4 = i & 127;
            float4 v = __ldcg(((const float4*)(hin + r * 512)) + c4);
            float* dst = h_s + r * 514 + c4 * 4;
            dst[0] = v.x; dst[1] = v.y; dst[2] = v.z; dst[3] = v.w;
        }
        __syncthreads();

        const ull* hp0 = (const ull*)(h_s + lane * 514);
        const ull* hp1 = (const ull*)(h_s + (lane + 32) * 514);
        ull a00 = 0, a01 = 0, a02 = 0, a03 = 0;
        ull a10 = 0, a11 = 0, a12 = 0, a13 = 0;
#pragma unroll 4
        for (int k2 = 0; k2 < 256; k2++) {
            ull h0 = hp0[k2], h1 = hp1[k2];
            ull w0 = wr0[k2], w1 = wr1[k2], w2v = wr2[k2], w3 = wr3[k2];
            a00 = fma2_(h0, w0, a00); a01 = fma2_(h0, w1, a01);
            a02 = fma2_(h0, w2v, a02); a03 = fma2_(h0, w3, a03);
            a10 = fma2_(h1, w0, a10); a11 = fma2_(h1, w1, a11);
            a12 = fma2_(h1, w2v, a12); a13 = fma2_(h1, w3, a13);
        }

        // epilogue: two batch rows per lane
        {
            int b = lane;
            const float* xr = p.xg + ((size_t)b * Tn + t_act) * 2048;
            float gi = sum2_(a00) + xr[j];
            float gf = sum2_(a01) + xr[512 + j];
            float gg = sum2_(a02) + xr[1024 + j];
            float go = sum2_(a03) + xr[1536 + j];
            cc0 = sig_(gf) * cc0 + sig_(gi) * tanhf(gg);
            float hv = sig_(go) * tanhf(cc0);
            hout[b * 512 + j] = hv;
            p.y[((size_t)b * Tn + t_act) * p.ystr + p.ycol + j] = hv;
        }
        {
            int b = lane + 32;
            const float* xr = p.xg + ((size_t)b * Tn + t_act) * 2048;
            float gi = sum2_(a10) + xr[j];
            float gf = sum2_(a11) + xr[512 + j];
            float gg = sum2_(a12) + xr[1024 + j];
            float go = sum2_(a13) + xr[1536 + j];
            cc1 = sig_(gf) * cc1 + sig_(gi) * tanhf(gg);
            float hv = sig_(go) * tanhf(cc1);
            hout[b * 512 + j] = hv;
            p.y[((size_t)b * Tn + t_act) * p.ystr + p.ycol + j] = hv;
        }

        // software grid barrier (all blocks co-resident)
        __threadfence();
        __syncthreads();
        if (tid == 0) {
            unsigned n = atomicAdd(&g_arr, 1u) + 1u;
            if (n == (unsigned)nb * (unsigned)(t + 1)) {
                atomicExch(&g_rel, (unsigned)(t + 1));
            }
            volatile unsigned* rp = &g_rel;
            while (*rp < (unsigned)(t + 1)) { }
            __threadfence();
        }
        __syncthreads();
    }

    if (p.cfin) {
        p.cfin[lane * 512 + j]        = cc0;
        p.cfin[(lane + 32) * 512 + j] = cc1;
    }
}

// ---------------- host orchestration ----------------
extern "C" void kernel_launch(void* const* d_in, const int* in_sizes, int n_in,
                              void* d_out, int out_size) {
    const int*   x   = (const int*)d_in[0];
    const float* emb = (const float*)d_in[1];
    auto F = [&](int i) { return (const float*)d_in[i]; };

    float *xgA, *xgB, *x1, *din, *yd0, *yd1;
    float *hA0, *hA1, *hB0, *hB1, *h0f, *c0f, *h0b, *c0b;
    cudaGetSymbolAddress((void**)&xgA, g_xgA);
    cudaGetSymbolAddress((void**)&xgB, g_xgB);
    cudaGetSymbolAddress((void**)&x1,  g_x1);
    cudaGetSymbolAddress((void**)&din, g_din);
    cudaGetSymbolAddress((void**)&yd0, g_yd0);
    cudaGetSymbolAddress((void**)&yd1, g_yd1);
    cudaGetSymbolAddress((void**)&hA0, g_hA0);
    cudaGetSymbolAddress((void**)&hA1, g_hA1);
    cudaGetSymbolAddress((void**)&hB0, g_hB0);
    cudaGetSymbolAddress((void**)&hB1, g_hB1);
    cudaGetSymbolAddress((void**)&h0f, g_h0f);
    cudaGetSymbolAddress((void**)&c0f, g_c0f);
    cudaGetSymbolAddress((void**)&h0b, g_h0b);
    cudaGetSymbolAddress((void**)&c0b, g_c0b);

    cudaFuncSetAttribute(k_scan, cudaFuncAttributeMaxDynamicSharedMemorySize, SMEM_SCAN);

    const int SN = 64 * 512;
    dim3 gGemm(2048 / 64, BT / 128);   // 128x64 tiles

    auto mkP = [](const float* xg, const float* Whh, const float* cin,
                  float* hb0, float* hb1, float* cfin,
                  float* y, int ycol, int ystr, int rev) {
        ScanP p; p.xg = xg; p.Whh = Whh; p.cin = cin;
        p.hb0 = hb0; p.hb1 = hb1; p.cfin = cfin;
        p.y = y; p.ycol = ycol; p.ystr = ystr; p.rev = rev;
        return p;
    };

    // prologue ordered (zeros/rst first) so ncu's fixed capture window
    // lands on an interesting kernel (embed/gemm) instead of k_zero.
    k_zero<<<128, 256>>>(hA0, SN);
    k_zero<<<128, 256>>>(hB0, SN);
    k_rst<<<1, 32>>>();

    // 1. embedding -> din[:, 0:256]
    k_embed<<<(BT * 64 + 255) / 256, 256>>>(x, emb, din);

    // 2. encoder layer 0 (fwd + bwd)
    k_gemm<<<gGemm, 256>>>(din, 1280, F(2), 256, F(4), F(5), xgA, 2048);
    k_gemm<<<gGemm, 256>>>(din, 1280, F(6), 256, F(8), F(9), xgB, 2048);
    {
        ScanP pa = mkP(xgA, F(3), nullptr, hA0, hA1, c0f, x1, 0, 1024, 0);
        ScanP pb = mkP(xgB, F(7), nullptr, hB0, hB1, c0b, x1, 512, 1024, 1);
        k_scan<<<dim3(64, 2), 256, SMEM_SCAN>>>(pa, pb, 128);
    }
    // final h of layer 0 is in buffer 0 (t=511 writes hb0)
    k_copy<<<128, 256>>>(h0f, hA0, SN);
    k_copy<<<128, 256>>>(h0b, hB0, SN);

    // 3. encoder layer 1 (fwd + bwd), outputs into din cols 256 / 768
    k_gemm<<<gGemm, 256>>>(x1, 1024, F(10), 1024, F(12), F(13), xgA, 2048);
    k_gemm<<<gGemm, 256>>>(x1, 1024, F(14), 1024, F(16), F(17), xgB, 2048);
    k_zero<<<128, 256>>>(hA0, SN);
    k_zero<<<128, 256>>>(hB0, SN);
    k_rst<<<1, 32>>>();
    {
        ScanP pa = mkP(xgA, F(11), nullptr, hA0, hA1, nullptr, din, 256, 1280, 0);
        ScanP pb = mkP(xgB, F(15), nullptr, hB0, hB1, nullptr, din, 768, 1280, 1);
        k_scan<<<dim3(64, 2), 256, SMEM_SCAN>>>(pa, pb, 128);
    }

    // 4. decoder layer 0 (init = enc l0 fwd final state)
    k_gemm<<<gGemm, 256>>>(din, 1280, F(18), 1280, F(20), F(21), xgA, 2048);
    k_copy<<<128, 256>>>(hA0, h0f, SN);
    k_rst<<<1, 32>>>();
    {
        ScanP pa = mkP(xgA, F(19), c0f, hA0, hA1, nullptr, yd0, 0, 512, 0);
        k_scan<<<dim3(64, 1), 256, SMEM_SCAN>>>(pa, pa, 64);
    }

    // 5. decoder layer 1 (init = enc l0 bwd final state)
    k_gemm<<<gGemm, 256>>>(yd0, 512, F(22), 512, F(24), F(25), xgA, 2048);
    k_copy<<<128, 256>>>(hA0, h0b, SN);
    k_rst<<<1, 32>>>();
    {
        ScanP pa = mkP(xgA, F(23), c0b, hA0, hA1, nullptr, yd1, 0, 512, 0);
        k_scan<<<dim3(64, 1), 256, SMEM_SCAN>>>(pa, pa, 64);
    }

    // 6. output projection: logits = yd1 @ out_W^T + out_b  (N = 128)
    k_gemm<<<dim3(128 / 64, BT / 128), 256>>>(yd1, 512, F(26), 512, F(27), nullptr,
                                              (float*)d_out, 128);
}